// round 4
// baseline (speedup 1.0000x reference)
#include <cuda_runtime.h>
#include <math.h>

// ---------------- problem constants ----------------
#define BATCH 4
#define DD 28
#define HH 28
#define WW 8
#define SP (DD*HH*WW)        // 6272
#define NSP (BATCH*SP)       // 25088
#define CMAX 128
#define DP 30
#define HP 30
#define WP 10
#define PSP (DP*HP*WP)       // 9000

typedef unsigned long long ull;

__device__ __forceinline__ ull pk(float a, float b) {
    ull r; asm("mov.b64 %0,{%1,%2};" : "=l"(r) : "f"(a), "f"(b)); return r;
}
__device__ __forceinline__ void upk(ull v, float& a, float& b) {
    asm("mov.b64 {%0,%1},%2;" : "=f"(a), "=f"(b) : "l"(v));
}
__device__ __forceinline__ ull ff2(ull a, ull b, ull c) {
    ull d; asm("fma.rn.f32x2 %0,%1,%2,%3;" : "=l"(d) : "l"(a), "l"(b), "l"(c)); return d;
}

// ---------------- scratch ----------------
__device__ float g_bufA[BATCH*SP*CMAX];
__device__ float g_bufB[BATCH*SP*CMAX];
__device__ float g_bufP[BATCH*PSP*CMAX];
__device__ float2 g_wpair[557280];
__device__ float  g_wdef[27*128*128];
__device__ float4 g_meta[27*NSP];
__device__ float g_ps[784*CMAX];
__device__ float g_pq[784*CMAX];
__device__ float2 g_bn[4][CMAX];

#define W1_OFF 0
#define W2_OFF 864
#define W3_OFF 56160
#define W4_OFF 277344

#define S1 864
#define S2 55296
#define S3 221184
#define S4 279936
#define S5 442368
#define WT_TOTAL (S1+S2+S3+S4+S5)

// ---------------- merged weight transpose ----------------
__global__ void wtrans_all_kernel(const float* __restrict__ w1, const float* __restrict__ w2,
                                  const float* __restrict__ w3, const float* __restrict__ w4,
                                  const float* __restrict__ w5) {
    int idx = blockIdx.x * blockDim.x + threadIdx.x;
    if (idx >= WT_TOTAL) return;
    const float* src; float2* dst; int CIN, COUT; int l = idx; int plain = 0;
    if (l < S1)              { src = w1; dst = g_wpair + W1_OFF; CIN = 1;   COUT = 32; }
    else if ((l -= S1) < S2) { src = w2; dst = g_wpair + W2_OFF; CIN = 32;  COUT = 64; }
    else if ((l -= S2) < S3) { src = w3; dst = g_wpair + W3_OFF; CIN = 64;  COUT = 128; }
    else if ((l -= S3) < S4) { src = w4; dst = g_wpair + W4_OFF; CIN = 128; COUT = 81; }
    else { l -= S4; src = w5; dst = nullptr; CIN = 128; COUT = 128; plain = 1; }
    int n = l % 27;
    int c = (l / 27) % CIN;
    int o = l / (27 * CIN);
    float v = src[l];
    if (plain) g_wdef[((size_t)n * 128 + c) * 128 + o] = v;
    else       dst[((size_t)n * CIN + c) * COUT + o] = make_float2(v, v);
}

// ---------------- tiled conv3d, channel-last ----------------
// GROUPS: split 4h-tile among thread groups (all threads useful).
// DTILE: d-slices per block (shares staged weights / doubles reuse).
template<int CIN, int COUT, int GROUPS, int DTILE, int BLOCKT,
         bool RELU, bool NCDHW_OUT, int BN_LAYER, bool STATS>
__global__ void conv_cl_kernel(const float* __restrict__ x, const float2* __restrict__ wp,
                               const float* __restrict__ bias, float* __restrict__ y) {
    constexpr int CH = (CIN < 16) ? CIN : 16;
    constexpr int NCH = CIN / CH;
    constexpr int PH = 4 / GROUPS;           // h-rows per thread
    constexpr int DQ = DD / DTILE;           // 28 or 14
    __shared__ float xs[DTILE][CH][18][12];

    int tid = threadIdx.x;
    int blk = blockIdx.x;
    int hb = blk % 7;
    int dq = (blk / 7) % DQ;
    int b  = blk / (7 * DQ);
    int h0 = hb * 4;
    int grp = (GROUPS > 1) ? (tid / COUT) : 0;
    int o   = (GROUPS > 1) ? (tid - grp * COUT) : ((tid < COUT) ? tid : 0);

    ull acc2[DTILE][PH][4];
    #pragma unroll
    for (int dt = 0; dt < DTILE; dt++)
        #pragma unroll
        for (int ph = 0; ph < PH; ph++)
            #pragma unroll
            for (int j = 0; j < 4; j++) acc2[dt][ph][j] = 0ull;

    for (int cc = 0; cc < NCH; cc++) {
        __syncthreads();
        for (int i = tid; i < DTILE * 180 * CH; i += BLOCKT) {
            int ci, rest;
            if (CH == 16) { ci = i & 15; rest = i >> 4; }
            else          { ci = i % CH; rest = i / CH; }
            int pos = rest % 180;
            int dt  = rest / 180;
            int zw = pos % 10;
            int zh = (pos / 10) % 6;
            int zd = pos / 60;
            int d = dq + dt * DQ;
            int gd = d + zd - 1, gh = h0 + zh - 1, gw = zw - 1;
            float v = 0.0f;
            int cg = cc * CH + ci;
            if ((unsigned)gd < DD && (unsigned)gh < HH && (unsigned)gw < WW) {
                v = x[((size_t)((b * DD + gd) * HH + gh) * WW + gw) * CIN + cg];
                if (BN_LAYER >= 0) { float2 t = g_bn[BN_LAYER][cg]; v = fmaf(v, t.x, t.y); }
            }
            xs[dt][ci][zd * 6 + zh][zw] = v;
        }
        __syncthreads();

        #pragma unroll
        for (int dt = 0; dt < DTILE; dt++) {
            for (int ci = 0; ci < CH; ci++) {
                int cglob = cc * CH + ci;
                #pragma unroll
                for (int zd = 0; zd < 3; zd++) {
                    #pragma unroll
                    for (int zl = 0; zl < PH + 2; zl++) {
                        const float2* row = (const float2*)&xs[dt][ci][zd * 6 + grp * PH + zl][0];
                        float2 e0 = row[0], e1 = row[1], e2 = row[2], e3 = row[3], e4 = row[4];
                        ull P[9];
                        P[0] = pk(e0.x, e0.y); P[2] = pk(e1.x, e1.y); P[4] = pk(e2.x, e2.y);
                        P[6] = pk(e3.x, e3.y); P[8] = pk(e4.x, e4.y);
                        P[1] = pk(e0.y, e1.x); P[3] = pk(e1.y, e2.x);
                        P[5] = pk(e2.y, e3.x); P[7] = pk(e3.y, e4.x);
                        #pragma unroll
                        for (int ph = 0; ph < PH; ph++) {
                            int kh1 = zl - ph;
                            if (kh1 < 0 || kh1 > 2) continue;
                            #pragma unroll
                            for (int kw1 = 0; kw1 < 3; kw1++) {
                                int n = zd * 9 + kh1 * 3 + kw1;
                                ull wv2 = *(const ull*)&wp[((size_t)n * CIN + cglob) * COUT + o];
                                #pragma unroll
                                for (int j = 0; j < 4; j++)
                                    acc2[dt][ph][j] = ff2(wv2, P[kw1 + 2 * j], acc2[dt][ph][j]);
                            }
                        }
                    }
                }
            }
        }
    }

    if (tid < GROUPS * COUT) {
        float bs = bias[o];
        float ssum = 0.f, sq = 0.f;
        #pragma unroll
        for (int dt = 0; dt < DTILE; dt++) {
            int d = dq + dt * DQ;
            #pragma unroll
            for (int ph = 0; ph < PH; ph++) {
                int h = h0 + grp * PH + ph;
                #pragma unroll
                for (int j = 0; j < 4; j++) {
                    float v0, v1; upk(acc2[dt][ph][j], v0, v1);
                    v0 += bs; v1 += bs;
                    if (RELU) { v0 = fmaxf(v0, 0.f); v1 = fmaxf(v1, 0.f); }
                    if (STATS) { ssum += v0 + v1; sq += v0 * v0 + v1 * v1; }
                    int pw = 2 * j;
                    if (NCDHW_OUT) {
                        size_t base = (size_t)(b * COUT + o) * SP + (size_t)(d * HH + h) * WW;
                        y[base + pw] = v0; y[base + pw + 1] = v1;
                    } else {
                        size_t base = ((size_t)((b * DD + d) * HH + h) * WW + pw) * COUT + o;
                        y[base] = v0; y[base + COUT] = v1;
                    }
                }
            }
        }
        if (STATS) { g_ps[blk * CMAX + tid] = ssum; g_pq[blk * CMAX + tid] = sq; }
    }
}

// ---------------- BN finalize (GROUPS-aware partial layout) ----------------
__global__ void bn_fin_kernel(int C, int nblk, int groups, const float* __restrict__ gma,
                              const float* __restrict__ bta, int layer) {
    int c = threadIdx.x;
    if (c >= C) return;
    float s = 0.f, q = 0.f;
    for (int i = 0; i < nblk; i++)
        for (int g = 0; g < groups; g++) {
            s += g_ps[i * CMAX + c + g * C];
            q += g_pq[i * CMAX + c + g * C];
        }
    float m = s / (float)NSP;
    float var = q / (float)NSP - m * m;
    float r = rsqrtf(var + 1e-5f);
    float sc = r * gma[c];
    g_bn[layer][c] = make_float2(sc, bta[c] - m * sc);
}

// ---------------- BN3 into padded channel-last buffer ----------------
__global__ void pad_apply_kernel(const float* __restrict__ src) {
    int idx = blockIdx.x * blockDim.x + threadIdx.x;
    if (idx >= NSP * CMAX) return;
    int c = idx & 127;
    int s = idx >> 7;
    int w = s & 7;
    int t = s >> 3;
    int h = t % HH; t /= HH;
    int d = t % DD;
    int b = t / DD;
    float2 bn = g_bn[2][c];
    size_t dst = ((size_t)((b * DP + d + 1) * HP + h + 1) * WP + (w + 1)) * CMAX + c;
    g_bufP[dst] = fmaf(src[idx], bn.x, bn.y);
}

// ---------------- sampling metadata ----------------
__global__ void meta_kernel(const float* __restrict__ off) {
    int idx = blockIdx.x * blockDim.x + threadIdx.x;
    if (idx >= 27 * NSP) return;
    int n = idx / NSP;
    int s = idx - n * NSP;
    int w = s & 7;
    int t = s >> 3;
    int h = t % HH; t /= HH;
    int d = t % DD;
    int b = t / DD;
    int kd = n / 9 - 1, kh = (n / 3) % 3 - 1, kw = n % 3 - 1;
    size_t obase = (size_t)b * 81 * SP + (size_t)((d * HH + h) * WW + w);
    float od  = off[obase + (size_t)n * SP];
    float oh  = off[obase + (size_t)(27 + n) * SP];
    float ow_ = off[obase + (size_t)(54 + n) * SP];
    float pd = fminf(fmaxf((float)(d + 1 + kd) + od, 0.f), 29.f);
    float ph = fminf(fmaxf((float)(h + 1 + kh) + oh, 0.f), 29.f);
    float pw = fminf(fmaxf((float)(w + 1 + kw) + ow_, 0.f), 9.f);
    float fd = fminf(fmaxf(floorf(pd), 0.f), 28.f);
    float fh = fminf(fmaxf(floorf(ph), 0.f), 28.f);
    float fw = fminf(fmaxf(floorf(pw), 0.f), 8.f);
    float td = fminf(fmaxf(pd - fd, 0.f), 1.f);
    float th = fminf(fmaxf(ph - fh, 0.f), 1.f);
    float tw = fminf(fmaxf(pw - fw, 0.f), 1.f);
    int base = ((b * DP + (int)fd) * HP + (int)fh) * WP + (int)fw;
    g_meta[idx] = make_float4(td, th, tw, __int_as_float(base));
}

// ---------------- deformable conv ----------------
__global__ void __launch_bounds__(128) deform_kernel(const float* __restrict__ db,
                                                     float* __restrict__ y) {
    __shared__ float s_tile[128 * 68];

    int tid = threadIdx.x;
    int posBase = blockIdx.x * 64;

    ull acc2[32];
    #pragma unroll
    for (int j = 0; j < 32; j++) acc2[j] = 0ull;

    for (int n = 0; n < 27; n++) {
        __syncthreads();
        const float4* mrow = g_meta + (size_t)n * NSP + posBase;
        for (int p = 0; p < 64; p += 2) {
            float vv[2];
            #pragma unroll
            for (int u = 0; u < 2; u++) {
                float4 m = mrow[p + u];
                int base = __float_as_int(m.w);
                float td = m.x, th = m.y, tw = m.z;
                float ad = 1.f - td, ah = 1.f - th, aw = 1.f - tw;
                float c00 = ad * ah, c01 = ad * th, c10 = td * ah, c11 = td * th;
                const float* ptr = g_bufP + (size_t)base * CMAX + tid;
                float v;
                v  = (c00 * aw) * ptr[0];
                v += (c00 * tw) * ptr[CMAX];
                v += (c01 * aw) * ptr[WP * CMAX];
                v += (c01 * tw) * ptr[(WP + 1) * CMAX];
                v += (c10 * aw) * ptr[HP * WP * CMAX];
                v += (c10 * tw) * ptr[(HP * WP + 1) * CMAX];
                v += (c11 * aw) * ptr[(HP * WP + WP) * CMAX];
                v += (c11 * tw) * ptr[(HP * WP + WP + 1) * CMAX];
                vv[u] = v;
            }
            *(float2*)(s_tile + tid * 68 + p) = make_float2(vv[0], vv[1]);
        }
        __syncthreads();

        const float* wrow = g_wdef + (size_t)n * 128 * 128;
        float wv = wrow[tid];
        for (int c = 0; c < 128; c++) {
            float wnext = (c < 127) ? wrow[(c + 1) * 128 + tid] : 0.f;
            ull wv2 = pk(wv, wv);
            const ulonglong2* st2 = (const ulonglong2*)(s_tile + c * 68);
            #pragma unroll
            for (int jj = 0; jj < 16; jj++) {
                ulonglong2 q = st2[jj];
                acc2[2 * jj]     = ff2(wv2, q.x, acc2[2 * jj]);
                acc2[2 * jj + 1] = ff2(wv2, q.y, acc2[2 * jj + 1]);
            }
            wv = wnext;
        }
    }

    float bs = db[tid];
    float ssum = 0.f, sq = 0.f;
    #pragma unroll
    for (int j = 0; j < 32; j++) {
        float v0, v1; upk(acc2[j], v0, v1);
        v0 = fmaxf(v0 + bs, 0.f); v1 = fmaxf(v1 + bs, 0.f);
        ssum += v0 + v1; sq += v0 * v0 + v1 * v1;
        int s0 = posBase + 2 * j;
        y[(size_t)s0 * CMAX + tid]       = v0;
        y[(size_t)(s0 + 1) * CMAX + tid] = v1;
    }
    g_ps[blockIdx.x * CMAX + tid] = ssum;
    g_pq[blockIdx.x * CMAX + tid] = sq;
}

// ---------------- head ----------------
__global__ void head_kernel(const float* __restrict__ y, const float* __restrict__ fcw,
                            const float* __restrict__ fcb, float* __restrict__ out) {
    int b = blockIdx.x;
    int c = threadIdx.x;
    const float* p = y + (size_t)b * SP * CMAX + c;
    float s = 0.f;
    for (int i = 0; i < SP; i++) s += p[(size_t)i * CMAX];
    __shared__ float pooled[128];
    __shared__ float logits[10];
    float2 bn = g_bn[3][c];
    pooled[c] = fmaf(s / (float)SP, bn.x, bn.y);
    __syncthreads();
    if (c < 10) {
        float l = fcb[c];
        for (int k = 0; k < 128; k++) l += pooled[k] * fcw[c * 128 + k];
        logits[c] = l;
    }
    __syncthreads();
    if (c == 0) {
        float mx = logits[0];
        for (int j = 1; j < 10; j++) mx = fmaxf(mx, logits[j]);
        float se = 0.f;
        for (int j = 0; j < 10; j++) se += expf(logits[j] - mx);
        float lse = mx + logf(se);
        for (int j = 0; j < 10; j++) out[b * 10 + j] = logits[j] - lse;
    }
}

// ---------------- launcher ----------------
extern "C" void kernel_launch(void* const* d_in, const int* in_sizes, int n_in,
                              void* d_out, int out_size) {
    const float* x   = (const float*)d_in[0];
    const float* c1w = (const float*)d_in[1];  const float* c1b = (const float*)d_in[2];
    const float* g1  = (const float*)d_in[3];  const float* b1  = (const float*)d_in[4];
    const float* c2w = (const float*)d_in[5];  const float* c2b = (const float*)d_in[6];
    const float* g2  = (const float*)d_in[7];  const float* b2  = (const float*)d_in[8];
    const float* c3w = (const float*)d_in[9];  const float* c3b = (const float*)d_in[10];
    const float* g3  = (const float*)d_in[11]; const float* b3  = (const float*)d_in[12];
    const float* ow  = (const float*)d_in[13]; const float* ob  = (const float*)d_in[14];
    const float* dw  = (const float*)d_in[15]; const float* db  = (const float*)d_in[16];
    const float* g4  = (const float*)d_in[17]; const float* b4  = (const float*)d_in[18];
    const float* fcw = (const float*)d_in[19]; const float* fcb = (const float*)d_in[20];

    float* out = (float*)d_out;
    float* offsets = out + BATCH * 10;

    float *bufA, *bufB, *bufP; float2* wpair;
    cudaGetSymbolAddress((void**)&bufA, g_bufA);
    cudaGetSymbolAddress((void**)&bufB, g_bufB);
    cudaGetSymbolAddress((void**)&bufP, g_bufP);
    cudaGetSymbolAddress((void**)&wpair, g_wpair);

    cudaMemsetAsync(bufP, 0, (size_t)BATCH * PSP * CMAX * sizeof(float));
    wtrans_all_kernel<<<(WT_TOTAL + 255) / 256, 256>>>(c1w, c2w, c3w, ow, dw);

    const int G784 = BATCH * 28 * 7;   // DTILE=1 grid
    const int G392 = BATCH * 14 * 7;   // DTILE=2 grid

    // layer 1: conv(1->32), GROUPS=4
    conv_cl_kernel<1, 32, 4, 1, 128, true, false, -1, true><<<G784, 128>>>(x, wpair + W1_OFF, c1b, bufA);
    bn_fin_kernel<<<1, 128>>>(32, G784, 4, g1, b1, 0);

    // layer 2: conv(32->64), GROUPS=2
    conv_cl_kernel<32, 64, 2, 1, 128, true, false, 0, true><<<G784, 128>>>(bufA, wpair + W2_OFF, c2b, bufB);
    bn_fin_kernel<<<1, 128>>>(64, G784, 2, g2, b2, 1);

    // layer 3: conv(64->128), DTILE=2
    conv_cl_kernel<64, 128, 1, 2, 128, true, false, 1, true><<<G392, 128>>>(bufB, wpair + W3_OFF, c3b, bufA);
    bn_fin_kernel<<<1, 128>>>(128, G392, 1, g3, b3, 2);

    pad_apply_kernel<<<(NSP * CMAX + 255) / 256, 256>>>(bufA);

    // offsets conv (128->81), DTILE=2, 96-thread blocks
    conv_cl_kernel<128, 81, 1, 2, 96, false, true, 2, false><<<G392, 96>>>(bufA, wpair + W4_OFF, ob, offsets);

    meta_kernel<<<(27 * NSP + 255) / 256, 256>>>(offsets);
    deform_kernel<<<NSP / 64, 128>>>(db, bufB);
    bn_fin_kernel<<<1, 128>>>(128, NSP / 64, 1, g4, b4, 3);

    head_kernel<<<BATCH, 128>>>(bufB, fcw, fcb, out);
}

// round 5
// speedup vs baseline: 1.0344x; 1.0344x over previous
#include <cuda_runtime.h>
#include <math.h>

// ---------------- problem constants ----------------
#define BATCH 4
#define DD 28
#define HH 28
#define WW 8
#define SP (DD*HH*WW)        // 6272
#define NSP (BATCH*SP)       // 25088
#define CMAX 128
#define DP 30
#define HP 30
#define WP 10
#define PSP (DP*HP*WP)       // 9000
#define PSTRIDE 256

typedef unsigned long long ull;

__device__ __forceinline__ ull pk(float a, float b) {
    ull r; asm("mov.b64 %0,{%1,%2};" : "=l"(r) : "f"(a), "f"(b)); return r;
}
__device__ __forceinline__ void upk(ull v, float& a, float& b) {
    asm("mov.b64 {%0,%1},%2;" : "=f"(a), "=f"(b) : "l"(v));
}
__device__ __forceinline__ ull ff2(ull a, ull b, ull c) {
    ull d; asm("fma.rn.f32x2 %0,%1,%2,%3;" : "=l"(d) : "l"(a), "l"(b), "l"(c)); return d;
}

// ---------------- scratch ----------------
__device__ float g_bufA[BATCH*SP*CMAX];
__device__ float g_bufB[BATCH*SP*CMAX];
__device__ float g_bufP[BATCH*PSP*CMAX];
__device__ float2 g_wpair[557280];
__device__ float  g_wdef[27*128*128];
__device__ float4 g_meta[27*NSP];
__device__ float g_ps[784*PSTRIDE];
__device__ float g_pq[784*PSTRIDE];
__device__ float2 g_bn[4][CMAX];

#define W1_OFF 0
#define W2_OFF 864
#define W3_OFF 56160
#define W4_OFF 277344

#define S1 864
#define S2 55296
#define S3 221184
#define S4 279936
#define S5 442368
#define WT_TOTAL (S1+S2+S3+S4+S5)

// ---------------- merged weight transpose ----------------
__global__ void wtrans_all_kernel(const float* __restrict__ w1, const float* __restrict__ w2,
                                  const float* __restrict__ w3, const float* __restrict__ w4,
                                  const float* __restrict__ w5) {
    int idx = blockIdx.x * blockDim.x + threadIdx.x;
    if (idx >= WT_TOTAL) return;
    const float* src; float2* dst; int CIN, COUT; int l = idx; int plain = 0;
    if (l < S1)              { src = w1; dst = g_wpair + W1_OFF; CIN = 1;   COUT = 32; }
    else if ((l -= S1) < S2) { src = w2; dst = g_wpair + W2_OFF; CIN = 32;  COUT = 64; }
    else if ((l -= S2) < S3) { src = w3; dst = g_wpair + W3_OFF; CIN = 64;  COUT = 128; }
    else if ((l -= S3) < S4) { src = w4; dst = g_wpair + W4_OFF; CIN = 128; COUT = 81; }
    else { l -= S4; src = w5; dst = nullptr; CIN = 128; COUT = 128; plain = 1; }
    int n = l % 27;
    int c = (l / 27) % CIN;
    int o = l / (27 * CIN);
    float v = src[l];
    if (plain) g_wdef[((size_t)n * 128 + c) * 128 + o] = v;
    else       dst[((size_t)n * CIN + c) * COUT + o] = make_float2(v, v);
}

// ---------------- tiled conv3d, channel-last ----------------
// GROUPS: split 4h-tile among thread groups; BLOCKT = blockDim (may exceed GROUPS*COUT).
template<int CIN, int COUT, int GROUPS, int BLOCKT,
         bool RELU, bool NCDHW_OUT, int BN_LAYER, bool STATS>
__global__ void conv_cl_kernel(const float* __restrict__ x, const float2* __restrict__ wp,
                               const float* __restrict__ bias, float* __restrict__ y) {
    constexpr int CH = (CIN < 16) ? CIN : 16;
    constexpr int NCH = CIN / CH;
    constexpr int PH = 4 / GROUPS;           // h-rows per thread
    __shared__ float xs[CH][18][12];

    int tid = threadIdx.x;
    int blk = blockIdx.x;
    int hb = blk % 7;
    int d  = (blk / 7) % DD;
    int b  = blk / (7 * DD);
    int h0 = hb * 4;
    int grp = tid / COUT;
    if (grp > GROUPS - 1) grp = GROUPS - 1;     // idle threads: safe indices
    int o = tid - grp * COUT;
    if (o >= COUT) o = 0;

    ull acc2[PH][4];
    #pragma unroll
    for (int ph = 0; ph < PH; ph++)
        #pragma unroll
        for (int j = 0; j < 4; j++) acc2[ph][j] = 0ull;

    for (int cc = 0; cc < NCH; cc++) {
        __syncthreads();
        for (int i = tid; i < 180 * CH; i += BLOCKT) {
            int ci, pos;
            if (CH == 16) { ci = i & 15; pos = i >> 4; }
            else          { ci = i % CH; pos = i / CH; }
            int zw = pos % 10;
            int zh = (pos / 10) % 6;
            int zd = pos / 60;
            int gd = d + zd - 1, gh = h0 + zh - 1, gw = zw - 1;
            float v = 0.0f;
            int cg = cc * CH + ci;
            if ((unsigned)gd < DD && (unsigned)gh < HH && (unsigned)gw < WW) {
                v = x[((size_t)((b * DD + gd) * HH + gh) * WW + gw) * CIN + cg];
                if (BN_LAYER >= 0) { float2 t = g_bn[BN_LAYER][cg]; v = fmaf(v, t.x, t.y); }
            }
            xs[ci][zd * 6 + zh][zw] = v;
        }
        __syncthreads();

        for (int ci = 0; ci < CH; ci++) {
            int cglob = cc * CH + ci;
            #pragma unroll
            for (int zd = 0; zd < 3; zd++) {
                #pragma unroll
                for (int zl = 0; zl < PH + 2; zl++) {
                    const float2* row = (const float2*)&xs[ci][zd * 6 + grp * PH + zl][0];
                    float2 e0 = row[0], e1 = row[1], e2 = row[2], e3 = row[3], e4 = row[4];
                    ull P[9];
                    P[0] = pk(e0.x, e0.y); P[2] = pk(e1.x, e1.y); P[4] = pk(e2.x, e2.y);
                    P[6] = pk(e3.x, e3.y); P[8] = pk(e4.x, e4.y);
                    P[1] = pk(e0.y, e1.x); P[3] = pk(e1.y, e2.x);
                    P[5] = pk(e2.y, e3.x); P[7] = pk(e3.y, e4.x);
                    #pragma unroll
                    for (int ph = 0; ph < PH; ph++) {
                        int kh1 = zl - ph;
                        if (kh1 < 0 || kh1 > 2) continue;
                        #pragma unroll
                        for (int kw1 = 0; kw1 < 3; kw1++) {
                            int n = zd * 9 + kh1 * 3 + kw1;
                            ull wv2 = *(const ull*)&wp[((size_t)n * CIN + cglob) * COUT + o];
                            #pragma unroll
                            for (int j = 0; j < 4; j++)
                                acc2[ph][j] = ff2(wv2, P[kw1 + 2 * j], acc2[ph][j]);
                        }
                    }
                }
            }
        }
    }

    if (tid < GROUPS * COUT) {
        float bs = bias[o];
        float ssum = 0.f, sq = 0.f;
        #pragma unroll
        for (int ph = 0; ph < PH; ph++) {
            int h = h0 + grp * PH + ph;
            #pragma unroll
            for (int j = 0; j < 4; j++) {
                float v0, v1; upk(acc2[ph][j], v0, v1);
                v0 += bs; v1 += bs;
                if (RELU) { v0 = fmaxf(v0, 0.f); v1 = fmaxf(v1, 0.f); }
                if (STATS) { ssum += v0 + v1; sq += v0 * v0 + v1 * v1; }
                int pw = 2 * j;
                if (NCDHW_OUT) {
                    size_t base = (size_t)(b * COUT + o) * SP + (size_t)(d * HH + h) * WW;
                    y[base + pw] = v0; y[base + pw + 1] = v1;
                } else {
                    size_t base = ((size_t)((b * DD + d) * HH + h) * WW + pw) * COUT + o;
                    y[base] = v0; y[base + COUT] = v1;
                }
            }
        }
        if (STATS) { g_ps[blk * PSTRIDE + tid] = ssum; g_pq[blk * PSTRIDE + tid] = sq; }
    }
}

// ---------------- BN finalize (GROUPS-aware partial layout) ----------------
__global__ void bn_fin_kernel(int C, int nblk, int groups, const float* __restrict__ gma,
                              const float* __restrict__ bta, int layer) {
    int c = threadIdx.x;
    if (c >= C) return;
    float s = 0.f, q = 0.f;
    for (int i = 0; i < nblk; i++)
        for (int g = 0; g < groups; g++) {
            s += g_ps[i * PSTRIDE + c + g * C];
            q += g_pq[i * PSTRIDE + c + g * C];
        }
    float m = s / (float)NSP;
    float var = q / (float)NSP - m * m;
    float r = rsqrtf(var + 1e-5f);
    float sc = r * gma[c];
    g_bn[layer][c] = make_float2(sc, bta[c] - m * sc);
}

// ---------------- BN3 into padded channel-last buffer ----------------
__global__ void pad_apply_kernel(const float* __restrict__ src) {
    int idx = blockIdx.x * blockDim.x + threadIdx.x;
    if (idx >= NSP * CMAX) return;
    int c = idx & 127;
    int s = idx >> 7;
    int w = s & 7;
    int t = s >> 3;
    int h = t % HH; t /= HH;
    int d = t % DD;
    int b = t / DD;
    float2 bn = g_bn[2][c];
    size_t dst = ((size_t)((b * DP + d + 1) * HP + h + 1) * WP + (w + 1)) * CMAX + c;
    g_bufP[dst] = fmaf(src[idx], bn.x, bn.y);
}

// ---------------- sampling metadata ----------------
__global__ void meta_kernel(const float* __restrict__ off) {
    int idx = blockIdx.x * blockDim.x + threadIdx.x;
    if (idx >= 27 * NSP) return;
    int n = idx / NSP;
    int s = idx - n * NSP;
    int w = s & 7;
    int t = s >> 3;
    int h = t % HH; t /= HH;
    int d = t % DD;
    int b = t / DD;
    int kd = n / 9 - 1, kh = (n / 3) % 3 - 1, kw = n % 3 - 1;
    size_t obase = (size_t)b * 81 * SP + (size_t)((d * HH + h) * WW + w);
    float od  = off[obase + (size_t)n * SP];
    float oh  = off[obase + (size_t)(27 + n) * SP];
    float ow_ = off[obase + (size_t)(54 + n) * SP];
    float pd = fminf(fmaxf((float)(d + 1 + kd) + od, 0.f), 29.f);
    float ph = fminf(fmaxf((float)(h + 1 + kh) + oh, 0.f), 29.f);
    float pw = fminf(fmaxf((float)(w + 1 + kw) + ow_, 0.f), 9.f);
    float fd = fminf(fmaxf(floorf(pd), 0.f), 28.f);
    float fh = fminf(fmaxf(floorf(ph), 0.f), 28.f);
    float fw = fminf(fmaxf(floorf(pw), 0.f), 8.f);
    float td = fminf(fmaxf(pd - fd, 0.f), 1.f);
    float th = fminf(fmaxf(ph - fh, 0.f), 1.f);
    float tw = fminf(fmaxf(pw - fw, 0.f), 1.f);
    int base = ((b * DP + (int)fd) * HP + (int)fh) * WP + (int)fw;
    g_meta[idx] = make_float4(td, th, tw, __int_as_float(base));
}

// ---------------- deformable conv (R3-exact) ----------------
__global__ void __launch_bounds__(128) deform_kernel(const float* __restrict__ db,
                                                     float* __restrict__ y) {
    __shared__ float s_tile[128 * 68];

    int tid = threadIdx.x;
    int posBase = blockIdx.x * 64;

    ull acc2[32];
    #pragma unroll
    for (int j = 0; j < 32; j++) acc2[j] = 0ull;

    for (int n = 0; n < 27; n++) {
        __syncthreads();
        const float4* mrow = g_meta + (size_t)n * NSP + posBase;
        for (int p = 0; p < 64; p++) {
            float4 m = mrow[p];
            int base = __float_as_int(m.w);
            float td = m.x, th = m.y, tw = m.z;
            float ad = 1.f - td, ah = 1.f - th, aw = 1.f - tw;
            float c00 = ad * ah, c01 = ad * th, c10 = td * ah, c11 = td * th;
            const float* ptr = g_bufP + (size_t)base * CMAX + tid;
            float v;
            v  = (c00 * aw) * ptr[0];
            v += (c00 * tw) * ptr[CMAX];
            v += (c01 * aw) * ptr[WP * CMAX];
            v += (c01 * tw) * ptr[(WP + 1) * CMAX];
            v += (c10 * aw) * ptr[HP * WP * CMAX];
            v += (c10 * tw) * ptr[(HP * WP + 1) * CMAX];
            v += (c11 * aw) * ptr[(HP * WP + WP) * CMAX];
            v += (c11 * tw) * ptr[(HP * WP + WP + 1) * CMAX];
            s_tile[tid * 68 + p] = v;
        }
        __syncthreads();

        const float* wrow = g_wdef + (size_t)n * 128 * 128;
        for (int c = 0; c < 128; c++) {
            float wv = wrow[c * 128 + tid];
            ull wv2 = pk(wv, wv);
            const ulonglong2* st2 = (const ulonglong2*)(s_tile + c * 68);
            #pragma unroll
            for (int jj = 0; jj < 16; jj++) {
                ulonglong2 q = st2[jj];
                acc2[2 * jj]     = ff2(wv2, q.x, acc2[2 * jj]);
                acc2[2 * jj + 1] = ff2(wv2, q.y, acc2[2 * jj + 1]);
            }
        }
    }

    float bs = db[tid];
    float ssum = 0.f, sq = 0.f;
    #pragma unroll
    for (int j = 0; j < 32; j++) {
        float v0, v1; upk(acc2[j], v0, v1);
        v0 = fmaxf(v0 + bs, 0.f); v1 = fmaxf(v1 + bs, 0.f);
        ssum += v0 + v1; sq += v0 * v0 + v1 * v1;
        int s0 = posBase + 2 * j;
        y[(size_t)s0 * CMAX + tid]       = v0;
        y[(size_t)(s0 + 1) * CMAX + tid] = v1;
    }
    g_ps[blockIdx.x * PSTRIDE + tid] = ssum;
    g_pq[blockIdx.x * PSTRIDE + tid] = sq;
}

// ---------------- head ----------------
__global__ void head_kernel(const float* __restrict__ y, const float* __restrict__ fcw,
                            const float* __restrict__ fcb, float* __restrict__ out) {
    int b = blockIdx.x;
    int c = threadIdx.x;
    const float* p = y + (size_t)b * SP * CMAX + c;
    float s = 0.f;
    for (int i = 0; i < SP; i++) s += p[(size_t)i * CMAX];
    __shared__ float pooled[128];
    __shared__ float logits[10];
    float2 bn = g_bn[3][c];
    pooled[c] = fmaf(s / (float)SP, bn.x, bn.y);
    __syncthreads();
    if (c < 10) {
        float l = fcb[c];
        for (int k = 0; k < 128; k++) l += pooled[k] * fcw[c * 128 + k];
        logits[c] = l;
    }
    __syncthreads();
    if (c == 0) {
        float mx = logits[0];
        for (int j = 1; j < 10; j++) mx = fmaxf(mx, logits[j]);
        float se = 0.f;
        for (int j = 0; j < 10; j++) se += expf(logits[j] - mx);
        float lse = mx + logf(se);
        for (int j = 0; j < 10; j++) out[b * 10 + j] = logits[j] - lse;
    }
}

// ---------------- launcher ----------------
extern "C" void kernel_launch(void* const* d_in, const int* in_sizes, int n_in,
                              void* d_out, int out_size) {
    const float* x   = (const float*)d_in[0];
    const float* c1w = (const float*)d_in[1];  const float* c1b = (const float*)d_in[2];
    const float* g1  = (const float*)d_in[3];  const float* b1  = (const float*)d_in[4];
    const float* c2w = (const float*)d_in[5];  const float* c2b = (const float*)d_in[6];
    const float* g2  = (const float*)d_in[7];  const float* b2  = (const float*)d_in[8];
    const float* c3w = (const float*)d_in[9];  const float* c3b = (const float*)d_in[10];
    const float* g3  = (const float*)d_in[11]; const float* b3  = (const float*)d_in[12];
    const float* ow  = (const float*)d_in[13]; const float* ob  = (const float*)d_in[14];
    const float* dw  = (const float*)d_in[15]; const float* db  = (const float*)d_in[16];
    const float* g4  = (const float*)d_in[17]; const float* b4  = (const float*)d_in[18];
    const float* fcw = (const float*)d_in[19]; const float* fcb = (const float*)d_in[20];

    float* out = (float*)d_out;
    float* offsets = out + BATCH * 10;

    float *bufA, *bufB, *bufP; float2* wpair;
    cudaGetSymbolAddress((void**)&bufA, g_bufA);
    cudaGetSymbolAddress((void**)&bufB, g_bufB);
    cudaGetSymbolAddress((void**)&bufP, g_bufP);
    cudaGetSymbolAddress((void**)&wpair, g_wpair);

    cudaMemsetAsync(bufP, 0, (size_t)BATCH * PSP * CMAX * sizeof(float));
    wtrans_all_kernel<<<(WT_TOTAL + 255) / 256, 256>>>(c1w, c2w, c3w, ow, dw);

    const int G784 = BATCH * 28 * 7;   // 784

    // layer 1: conv(1->32), GROUPS=4, 128 threads
    conv_cl_kernel<1, 32, 4, 128, true, false, -1, true><<<G784, 128>>>(x, wpair + W1_OFF, c1b, bufA);
    bn_fin_kernel<<<1, 128>>>(32, G784, 4, g1, b1, 0);

    // layer 2: conv(32->64), GROUPS=4, 256 threads
    conv_cl_kernel<32, 64, 4, 256, true, false, 0, true><<<G784, 256>>>(bufA, wpair + W2_OFF, c2b, bufB);
    bn_fin_kernel<<<1, 128>>>(64, G784, 4, g2, b2, 1);

    // layer 3: conv(64->128), GROUPS=2, 256 threads
    conv_cl_kernel<64, 128, 2, 256, true, false, 1, true><<<G784, 256>>>(bufB, wpair + W3_OFF, c3b, bufA);
    bn_fin_kernel<<<1, 128>>>(128, G784, 2, g3, b3, 2);

    pad_apply_kernel<<<(NSP * CMAX + 255) / 256, 256>>>(bufA);

    // offsets conv (128->81), GROUPS=2, 192 threads (162 active)
    conv_cl_kernel<128, 81, 2, 192, false, true, 2, false><<<G784, 192>>>(bufA, wpair + W4_OFF, ob, offsets);

    meta_kernel<<<(27 * NSP + 255) / 256, 256>>>(offsets);
    deform_kernel<<<NSP / 64, 128>>>(db, bufB);
    bn_fin_kernel<<<1, 128>>>(128, NSP / 64, 1, g4, b4, 3);

    head_kernel<<<BATCH, 128>>>(bufB, fcw, fcb, out);
}

// round 6
// speedup vs baseline: 1.4727x; 1.4237x over previous
#include <cuda_runtime.h>
#include <math.h>

// ---------------- problem constants ----------------
#define BATCH 4
#define DD 28
#define HH 28
#define WW 8
#define SP (DD*HH*WW)        // 6272
#define NSP (BATCH*SP)       // 25088 = 196*128
#define CMAX 128

typedef unsigned long long ull;

// ---------------- packed f32x2 helpers ----------------
__device__ __forceinline__ ull pk(float a, float b) {
    ull r; asm("mov.b64 %0,{%1,%2};" : "=l"(r) : "f"(a), "f"(b)); return r;
}
__device__ __forceinline__ void upk(ull v, float& a, float& b) {
    asm("mov.b64 {%0,%1},%2;" : "=f"(a), "=f"(b) : "l"(v));
}
__device__ __forceinline__ ull ff2(ull a, ull b, ull c) {
    ull d; asm("fma.rn.f32x2 %0,%1,%2,%3;" : "=l"(d) : "l"(a), "l"(b), "l"(c)); return d;
}

// ---------------- scratch (static device, no allocs) ----------------
__device__ float g_bufA[BATCH*SP*CMAX];   // activations channel-last [b][sp][c]
__device__ float g_bufB[BATCH*SP*CMAX];
__device__ float2 g_wpair[1000000];       // all transposed weights, duplicated pairs
__device__ float g_mean[CMAX];
__device__ float g_rstd[CMAX];
__device__ float g_ps[784*CMAX];          // BN partial sums (deterministic)
__device__ float g_pq[784*CMAX];

// weight region offsets (in float2 elements)
#define W1_OFF 0                         // 27*1*32   = 864
#define W2_OFF 864                       // 27*32*64  = 55296
#define W3_OFF 56160                     // 27*64*128 = 221184
#define W4_OFF 277344                    // 27*128*81 = 279936
#define W5_OFF 557280                    // 27*128*128= 442368  (end 999648)

#define S1 864
#define S2 55296
#define S3 221184
#define S4 279936
#define S5 442368
#define WT_TOTAL (S1+S2+S3+S4+S5)

// ---------------- merged weight transpose: (O,CIN,27) -> pairs [n][ci][o] ----------------
__global__ void wtrans_all_kernel(const float* __restrict__ w1, const float* __restrict__ w2,
                                  const float* __restrict__ w3, const float* __restrict__ w4,
                                  const float* __restrict__ w5) {
    int idx = blockIdx.x * blockDim.x + threadIdx.x;
    if (idx >= WT_TOTAL) return;
    const float* src; float2* dst; int CIN, COUT; int l = idx;
    if (l < S1)              { src = w1; dst = g_wpair + W1_OFF; CIN = 1;   COUT = 32; }
    else if ((l -= S1) < S2) { src = w2; dst = g_wpair + W2_OFF; CIN = 32;  COUT = 64; }
    else if ((l -= S2) < S3) { src = w3; dst = g_wpair + W3_OFF; CIN = 64;  COUT = 128; }
    else if ((l -= S3) < S4) { src = w4; dst = g_wpair + W4_OFF; CIN = 128; COUT = 81; }
    else { l -= S4; src = w5; dst = g_wpair + W5_OFF; CIN = 128; COUT = 128; }
    int n = l % 27;
    int c = (l / 27) % CIN;
    int o = l / (27 * CIN);
    float v = src[l];
    dst[((size_t)n * CIN + c) * COUT + o] = make_float2(v, v);
}

// ---------------- tiled conv3d, channel-last, f32x2 inner, hoisted weights ----------------
// block: 128 threads, tile: 4h x 8w at fixed d. grid = B*D*(H/4) = 784
// GROUPS splits the 4 h-rows among thread groups (o = tid % COUT within group).
template<int CIN, int COUT, int GROUPS, bool RELU, bool NCDHW_OUT>
__global__ void conv_cl_kernel(const float* __restrict__ x, const float2* __restrict__ wp,
                               const float* __restrict__ bias, float* __restrict__ y) {
    constexpr int CH = (CIN < 16) ? CIN : 16;
    constexpr int NCH = CIN / CH;
    constexpr int PH = 4 / GROUPS;           // h-rows per thread
    __shared__ float xs[CH][18][12];   // [ci][zd*6+zh][zw padded 10->12]

    int tid = threadIdx.x;
    int blk = blockIdx.x;
    int hb = blk % 7;
    int d  = (blk / 7) % DD;
    int b  = blk / (7 * DD);
    int h0 = hb * 4;
    int grp = tid / COUT;
    if (grp > GROUPS - 1) grp = GROUPS - 1;
    int o = tid - grp * COUT;
    if (o >= COUT) o = 0;

    ull acc2[PH][4];
    #pragma unroll
    for (int ph = 0; ph < PH; ph++)
        #pragma unroll
        for (int j = 0; j < 4; j++) acc2[ph][j] = 0ull;

    for (int cc = 0; cc < NCH; cc++) {
        __syncthreads();
        // stage input tile (zero-padded halo), coalesced over ci
        for (int i = tid; i < 180 * CH; i += 128) {
            int ci, pos;
            if (CH == 16) { ci = i & 15; pos = i >> 4; }
            else          { ci = i % CH; pos = i / CH; }
            int zw = pos % 10;
            int zh = (pos / 10) % 6;
            int zd = pos / 60;
            int gd = d + zd - 1, gh = h0 + zh - 1, gw = zw - 1;
            float v = 0.0f;
            if ((unsigned)gd < DD && (unsigned)gh < HH && (unsigned)gw < WW)
                v = x[((size_t)((b * DD + gd) * HH + gh) * WW + gw) * CIN + cc * CH + ci];
            xs[ci][zd * 6 + zh][zw] = v;
        }
        __syncthreads();

        for (int ci = 0; ci < CH; ci++) {
            int cglob = cc * CH + ci;
            #pragma unroll
            for (int zd = 0; zd < 3; zd++) {
                // hoist the 9 taps of this zd-plane into registers (one LDG each)
                ull wreg[9];
                #pragma unroll
                for (int t = 0; t < 9; t++)
                    wreg[t] = *(const ull*)&wp[((size_t)(zd * 9 + t) * CIN + cglob) * COUT + o];
                #pragma unroll
                for (int zl = 0; zl < PH + 2; zl++) {
                    const float2* row = (const float2*)&xs[ci][zd * 6 + grp * PH + zl][0];
                    float2 e0 = row[0], e1 = row[1], e2 = row[2], e3 = row[3], e4 = row[4];
                    ull P[9];
                    P[0] = pk(e0.x, e0.y); P[2] = pk(e1.x, e1.y); P[4] = pk(e2.x, e2.y);
                    P[6] = pk(e3.x, e3.y); P[8] = pk(e4.x, e4.y);
                    P[1] = pk(e0.y, e1.x); P[3] = pk(e1.y, e2.x);
                    P[5] = pk(e2.y, e3.x); P[7] = pk(e3.y, e4.x);
                    #pragma unroll
                    for (int ph = 0; ph < PH; ph++) {
                        int kh1 = zl - ph;               // kh+1
                        if (kh1 < 0 || kh1 > 2) continue; // constant-folds
                        #pragma unroll
                        for (int kw1 = 0; kw1 < 3; kw1++) {
                            ull wv2 = wreg[kh1 * 3 + kw1];
                            #pragma unroll
                            for (int j = 0; j < 4; j++)
                                acc2[ph][j] = ff2(wv2, P[kw1 + 2 * j], acc2[ph][j]);
                        }
                    }
                }
            }
        }
    }

    if (tid < GROUPS * COUT) {
        float bs = bias[o];
        #pragma unroll
        for (int ph = 0; ph < PH; ph++) {
            int h = h0 + grp * PH + ph;
            #pragma unroll
            for (int j = 0; j < 4; j++) {
                float v0, v1; upk(acc2[ph][j], v0, v1);
                v0 += bs; v1 += bs;
                if (RELU) { v0 = fmaxf(v0, 0.f); v1 = fmaxf(v1, 0.f); }
                int pw = 2 * j;
                if (NCDHW_OUT) {
                    size_t base = (size_t)(b * COUT + o) * SP + (size_t)(d * HH + h) * WW;
                    y[base + pw] = v0; y[base + pw + 1] = v1;
                } else {
                    size_t base = ((size_t)((b * DD + d) * HH + h) * WW + pw) * COUT + o;
                    y[base] = v0; y[base + COUT] = v1;
                }
            }
        }
    }
}

// ---------------- BN: deterministic two-stage stats (channel-last) ----------------
__global__ void bn_part_kernel(const float* __restrict__ y, int C) {
    int blk = blockIdx.x;       // 196 position chunks of 128
    int c = threadIdx.x;
    if (c >= C) return;
    float s = 0.f, q = 0.f;
    int base = blk * 128;
    for (int i = 0; i < 128; i++) {
        float v = y[(size_t)(base + i) * C + c];
        s += v; q += v * v;
    }
    g_ps[blk * CMAX + c] = s;
    g_pq[blk * CMAX + c] = q;
}

__global__ void bn_fin_kernel(int C) {
    int c = threadIdx.x;
    if (c >= C) return;
    float s = 0.f, q = 0.f;
    for (int i = 0; i < 196; i++) { s += g_ps[i * CMAX + c]; q += g_pq[i * CMAX + c]; }
    float m = s / (float)NSP;
    float var = q / (float)NSP - m * m;
    g_mean[c] = m;
    g_rstd[c] = rsqrtf(var + 1e-5f);
}

__global__ void bn_apply_kernel(float* __restrict__ y, const float* __restrict__ gma,
                                const float* __restrict__ bta, int C) {
    int idx = blockIdx.x * blockDim.x + threadIdx.x;
    if (idx >= NSP * C) return;
    int c = idx % C;
    y[idx] = (y[idx] - g_mean[c]) * g_rstd[c] * gma[c] + bta[c];
}

// ---------------- deformable conv (channel-last in/out), f32x2 GEMV ----------------
__global__ void deform_kernel(const float* __restrict__ ht,   // channel-last h3 [pos][128]
                              const float* __restrict__ off,  // (B,81,D,H,W) NCDHW
                              const float2* __restrict__ wp,  // [n][c][o] duplicated pairs
                              const float* __restrict__ db,
                              float* __restrict__ y) {        // channel-last out
    __shared__ float s_tile[128 * 36];     // [c][p], row stride 36 floats (144B)
    __shared__ int   s_qd[32], s_qh[32], s_qw[32];
    __shared__ float s_td[32], s_th[32], s_tw[32];

    int tid = threadIdx.x;
    int posBase = blockIdx.x * 32;

    ull acc2[16];
    #pragma unroll
    for (int j = 0; j < 16; j++) acc2[j] = 0ull;

    for (int n = 0; n < 27; n++) {
        int kd = n / 9 - 1, kh = (n / 3) % 3 - 1, kw = n % 3 - 1;
        __syncthreads();
        if (tid < 32) {
            int s = posBase + tid;
            int w = s & 7;
            int t = s >> 3;
            int h = t % HH; t /= HH;
            int d = t % DD;
            int b = t / DD;
            size_t obase = (size_t)b * 81 * SP + (size_t)((d * HH + h) * WW + w);
            float od  = off[obase + (size_t)n * SP];
            float oh  = off[obase + (size_t)(27 + n) * SP];
            float ow_ = off[obase + (size_t)(54 + n) * SP];
            float pd = fminf(fmaxf((float)(d + 1 + kd) + od, 0.f), 29.f);
            float ph = fminf(fmaxf((float)(h + 1 + kh) + oh, 0.f), 29.f);
            float pw = fminf(fmaxf((float)(w + 1 + kw) + ow_, 0.f), 9.f);
            float fd = fminf(fmaxf(floorf(pd), 0.f), 28.f);
            float fh = fminf(fmaxf(floorf(ph), 0.f), 28.f);
            float fw = fminf(fmaxf(floorf(pw), 0.f), 8.f);
            s_qd[tid] = (int)fd; s_td[tid] = fminf(fmaxf(pd - fd, 0.f), 1.f);
            s_qh[tid] = (int)fh; s_th[tid] = fminf(fmaxf(ph - fh, 0.f), 1.f);
            s_qw[tid] = (int)fw; s_tw[tid] = fminf(fmaxf(pw - fw, 0.f), 1.f);
        }
        __syncthreads();

        // sampling: thread = channel, loop positions
        for (int p = 0; p < 32; p++) {
            int s = posBase + p;
            int b = s / SP;
            int qd = s_qd[p], qh = s_qh[p], qw = s_qw[p];
            float td = s_td[p], th = s_th[p], tw = s_tw[p];
            float v = 0.f;
            #pragma unroll
            for (int i = 0; i < 2; i++) {
                int zd = qd + i - 1;
                if ((unsigned)zd >= DD) continue;
                float gd = i ? td : (1.f - td);
                #pragma unroll
                for (int j = 0; j < 2; j++) {
                    int zh = qh + j - 1;
                    if ((unsigned)zh >= HH) continue;
                    float gdh = gd * (j ? th : (1.f - th));
                    #pragma unroll
                    for (int k = 0; k < 2; k++) {
                        int zw = qw + k - 1;
                        if ((unsigned)zw >= WW) continue;
                        float g = gdh * (k ? tw : (1.f - tw));
                        size_t base = (size_t)((b * DD + zd) * HH + zh) * WW + zw;
                        v += g * ht[base * CMAX + tid];
                    }
                }
            }
            s_tile[tid * 36 + p] = v;
        }
        __syncthreads();

        // GEMV: thread = output channel; fully unrolled over p -> acc stays in regs
        const float2* wrow = wp + (size_t)n * 128 * 128;
        for (int c = 0; c < 128; c++) {
            ull wv2 = *(const ull*)&wrow[c * 128 + tid];
            const ull* st = (const ull*)(s_tile + c * 36);
            #pragma unroll
            for (int j = 0; j < 16; j++)
                acc2[j] = ff2(wv2, st[j], acc2[j]);
        }
    }

    float bs = db[tid];
    #pragma unroll
    for (int j = 0; j < 16; j++) {
        float v0, v1; upk(acc2[j], v0, v1);
        int s0 = posBase + 2 * j;
        y[(size_t)s0 * CMAX + tid]       = fmaxf(v0 + bs, 0.f);
        y[(size_t)(s0 + 1) * CMAX + tid] = fmaxf(v1 + bs, 0.f);
    }
}

// ---------------- global avg pool + FC + log_softmax (channel-last) ----------------
__global__ void head_kernel(const float* __restrict__ y, const float* __restrict__ fcw,
                            const float* __restrict__ fcb, float* __restrict__ out) {
    int b = blockIdx.x;
    int c = threadIdx.x;   // 128
    const float* p = y + (size_t)b * SP * CMAX + c;
    float s = 0.f;
    for (int i = 0; i < SP; i++) s += p[(size_t)i * CMAX];
    __shared__ float pooled[128];
    __shared__ float logits[10];
    pooled[c] = s / (float)SP;
    __syncthreads();
    if (c < 10) {
        float l = fcb[c];
        for (int k = 0; k < 128; k++) l += pooled[k] * fcw[c * 128 + k];
        logits[c] = l;
    }
    __syncthreads();
    if (c == 0) {
        float mx = logits[0];
        for (int j = 1; j < 10; j++) mx = fmaxf(mx, logits[j]);
        float se = 0.f;
        for (int j = 0; j < 10; j++) se += expf(logits[j] - mx);
        float lse = mx + logf(se);
        for (int j = 0; j < 10; j++) out[b * 10 + j] = logits[j] - lse;
    }
}

// ---------------- launcher ----------------
extern "C" void kernel_launch(void* const* d_in, const int* in_sizes, int n_in,
                              void* d_out, int out_size) {
    const float* x   = (const float*)d_in[0];
    const float* c1w = (const float*)d_in[1];  const float* c1b = (const float*)d_in[2];
    const float* g1  = (const float*)d_in[3];  const float* b1  = (const float*)d_in[4];
    const float* c2w = (const float*)d_in[5];  const float* c2b = (const float*)d_in[6];
    const float* g2  = (const float*)d_in[7];  const float* b2  = (const float*)d_in[8];
    const float* c3w = (const float*)d_in[9];  const float* c3b = (const float*)d_in[10];
    const float* g3  = (const float*)d_in[11]; const float* b3  = (const float*)d_in[12];
    const float* ow  = (const float*)d_in[13]; const float* ob  = (const float*)d_in[14];
    const float* dw  = (const float*)d_in[15]; const float* db  = (const float*)d_in[16];
    const float* g4  = (const float*)d_in[17]; const float* b4  = (const float*)d_in[18];
    const float* fcw = (const float*)d_in[19]; const float* fcb = (const float*)d_in[20];

    float* out = (float*)d_out;
    float* offsets = out + BATCH * 10;   // logits first, then offsets (NCDHW)

    float *bufA, *bufB; float2* wpair;
    cudaGetSymbolAddress((void**)&bufA, g_bufA);
    cudaGetSymbolAddress((void**)&bufB, g_bufB);
    cudaGetSymbolAddress((void**)&wpair, g_wpair);

    auto grid = [](int total) { return (total + 255) / 256; };

    wtrans_all_kernel<<<(WT_TOTAL + 255) / 256, 256>>>(c1w, c2w, c3w, ow, dw);

    const int CBLK = BATCH * DD * (HH / 4);   // 784

    // layer 1: conv(1->32)+relu, BN   (GROUPS=4, all 128 threads useful)
    conv_cl_kernel<1, 32, 4, true, false><<<CBLK, 128>>>(x, wpair + W1_OFF, c1b, bufA);
    bn_part_kernel<<<196, 128>>>(bufA, 32);
    bn_fin_kernel<<<1, 128>>>(32);
    bn_apply_kernel<<<grid(NSP*32), 256>>>(bufA, g1, b1, 32);

    // layer 2: conv(32->64)+relu, BN   (GROUPS=2 @128thr — measured-best config)
    conv_cl_kernel<32, 64, 2, true, false><<<CBLK, 128>>>(bufA, wpair + W2_OFF, c2b, bufB);
    bn_part_kernel<<<196, 128>>>(bufB, 64);
    bn_fin_kernel<<<1, 128>>>(64);
    bn_apply_kernel<<<grid(NSP*64), 256>>>(bufB, g2, b2, 64);

    // layer 3: conv(64->128)+relu, BN
    conv_cl_kernel<64, 128, 1, true, false><<<CBLK, 128>>>(bufB, wpair + W3_OFF, c3b, bufA);
    bn_part_kernel<<<196, 128>>>(bufA, 128);
    bn_fin_kernel<<<1, 128>>>(128);
    bn_apply_kernel<<<grid(NSP*128), 256>>>(bufA, g3, b3, 128);

    // offsets conv (128->81), no relu, NCDHW straight into output buffer
    conv_cl_kernel<128, 81, 1, false, true><<<CBLK, 128>>>(bufA, wpair + W4_OFF, ob, offsets);

    // deformable conv (128->128) + relu, then BN
    deform_kernel<<<NSP / 32, 128>>>(bufA, offsets, wpair + W5_OFF, db, bufB);
    bn_part_kernel<<<196, 128>>>(bufB, 128);
    bn_fin_kernel<<<1, 128>>>(128);
    bn_apply_kernel<<<grid(NSP*128), 256>>>(bufB, g4, b4, 128);

    // pool + fc + log_softmax
    head_kernel<<<BATCH, 128>>>(bufB, fcw, fcb, out);
}

// round 7
// speedup vs baseline: 1.5504x; 1.0528x over previous
#include <cuda_runtime.h>
#include <math.h>

// ---------------- problem constants ----------------
#define BATCH 4
#define DD 28
#define HH 28
#define WW 8
#define SP (DD*HH*WW)        // 6272
#define NSP (BATCH*SP)       // 25088 = 196*128
#define CMAX 128

typedef unsigned long long ull;

// ---------------- packed f32x2 helpers ----------------
__device__ __forceinline__ ull pk(float a, float b) {
    ull r; asm("mov.b64 %0,{%1,%2};" : "=l"(r) : "f"(a), "f"(b)); return r;
}
__device__ __forceinline__ void upk(ull v, float& a, float& b) {
    asm("mov.b64 {%0,%1},%2;" : "=f"(a), "=f"(b) : "l"(v));
}
__device__ __forceinline__ ull ff2(ull a, ull b, ull c) {
    ull d; asm("fma.rn.f32x2 %0,%1,%2,%3;" : "=l"(d) : "l"(a), "l"(b), "l"(c)); return d;
}

// ---------------- scratch (static device, no allocs) ----------------
__device__ float g_bufA[BATCH*SP*CMAX];   // activations channel-last [b][sp][c]
__device__ float g_bufB[BATCH*SP*CMAX];
__device__ float2 g_wpair[1000000];       // all transposed weights, duplicated pairs
__device__ float g_mean[CMAX];
__device__ float g_rstd[CMAX];
__device__ float g_ps[784*CMAX];          // BN partial sums (deterministic)
__device__ float g_pq[784*CMAX];

// weight region offsets (in float2 elements)
#define W1_OFF 0                         // 27*1*32   = 864
#define W2_OFF 864                       // 27*32*64  = 55296
#define W3_OFF 56160                     // 27*64*128 = 221184
#define W4_OFF 277344                    // 27*128*81 = 279936
#define W5_OFF 557280                    // 27*128*128= 442368  (end 999648)

#define S1 864
#define S2 55296
#define S3 221184
#define S4 279936
#define S5 442368
#define WT_TOTAL (S1+S2+S3+S4+S5)

// ---------------- merged weight transpose: (O,CIN,27) -> pairs [n][ci][o] ----------------
__global__ void wtrans_all_kernel(const float* __restrict__ w1, const float* __restrict__ w2,
                                  const float* __restrict__ w3, const float* __restrict__ w4,
                                  const float* __restrict__ w5) {
    int idx = blockIdx.x * blockDim.x + threadIdx.x;
    if (idx >= WT_TOTAL) return;
    const float* src; float2* dst; int CIN, COUT; int l = idx;
    if (l < S1)              { src = w1; dst = g_wpair + W1_OFF; CIN = 1;   COUT = 32; }
    else if ((l -= S1) < S2) { src = w2; dst = g_wpair + W2_OFF; CIN = 32;  COUT = 64; }
    else if ((l -= S2) < S3) { src = w3; dst = g_wpair + W3_OFF; CIN = 64;  COUT = 128; }
    else if ((l -= S3) < S4) { src = w4; dst = g_wpair + W4_OFF; CIN = 128; COUT = 81; }
    else { l -= S4; src = w5; dst = g_wpair + W5_OFF; CIN = 128; COUT = 128; }
    int n = l % 27;
    int c = (l / 27) % CIN;
    int o = l / (27 * CIN);
    float v = src[l];
    dst[((size_t)n * CIN + c) * COUT + o] = make_float2(v, v);
}

// ---------------- tiled conv3d, channel-last, f32x2 inner, hoisted weights ----------------
// BLOCKT threads, tile: 4h x 8w at fixed d. grid = B*D*(H/4) = 784
template<int CIN, int COUT, int GROUPS, int BLOCKT, bool RELU, bool NCDHW_OUT>
__global__ void conv_cl_kernel(const float* __restrict__ x, const float2* __restrict__ wp,
                               const float* __restrict__ bias, float* __restrict__ y) {
    constexpr int CH = (CIN < 16) ? CIN : 16;
    constexpr int NCH = CIN / CH;
    constexpr int PH = 4 / GROUPS;           // h-rows per thread
    __shared__ float xs[CH][18][12];   // [ci][zd*6+zh][zw padded 10->12]

    int tid = threadIdx.x;
    int blk = blockIdx.x;
    int hb = blk % 7;
    int d  = (blk / 7) % DD;
    int b  = blk / (7 * DD);
    int h0 = hb * 4;
    int grp = tid / COUT;
    if (grp > GROUPS - 1) grp = GROUPS - 1;
    int o = tid - grp * COUT;
    if (o >= COUT) o = 0;

    ull acc2[PH][4];
    #pragma unroll
    for (int ph = 0; ph < PH; ph++)
        #pragma unroll
        for (int j = 0; j < 4; j++) acc2[ph][j] = 0ull;

    for (int cc = 0; cc < NCH; cc++) {
        __syncthreads();
        // stage input tile (zero-padded halo), coalesced over ci
        for (int i = tid; i < 180 * CH; i += BLOCKT) {
            int ci, pos;
            if (CH == 16) { ci = i & 15; pos = i >> 4; }
            else          { ci = i % CH; pos = i / CH; }
            int zw = pos % 10;
            int zh = (pos / 10) % 6;
            int zd = pos / 60;
            int gd = d + zd - 1, gh = h0 + zh - 1, gw = zw - 1;
            float v = 0.0f;
            if ((unsigned)gd < DD && (unsigned)gh < HH && (unsigned)gw < WW)
                v = x[((size_t)((b * DD + gd) * HH + gh) * WW + gw) * CIN + cc * CH + ci];
            xs[ci][zd * 6 + zh][zw] = v;
        }
        __syncthreads();

        for (int ci = 0; ci < CH; ci++) {
            int cglob = cc * CH + ci;
            #pragma unroll
            for (int zd = 0; zd < 3; zd++) {
                // hoist the 9 taps of this zd-plane into registers (one LDG each)
                ull wreg[9];
                #pragma unroll
                for (int t = 0; t < 9; t++)
                    wreg[t] = *(const ull*)&wp[((size_t)(zd * 9 + t) * CIN + cglob) * COUT + o];
                #pragma unroll
                for (int zl = 0; zl < PH + 2; zl++) {
                    const float2* row = (const float2*)&xs[ci][zd * 6 + grp * PH + zl][0];
                    float2 e0 = row[0], e1 = row[1], e2 = row[2], e3 = row[3], e4 = row[4];
                    ull P[9];
                    P[0] = pk(e0.x, e0.y); P[2] = pk(e1.x, e1.y); P[4] = pk(e2.x, e2.y);
                    P[6] = pk(e3.x, e3.y); P[8] = pk(e4.x, e4.y);
                    P[1] = pk(e0.y, e1.x); P[3] = pk(e1.y, e2.x);
                    P[5] = pk(e2.y, e3.x); P[7] = pk(e3.y, e4.x);
                    #pragma unroll
                    for (int ph = 0; ph < PH; ph++) {
                        int kh1 = zl - ph;               // kh+1
                        if (kh1 < 0 || kh1 > 2) continue; // constant-folds
                        #pragma unroll
                        for (int kw1 = 0; kw1 < 3; kw1++) {
                            ull wv2 = wreg[kh1 * 3 + kw1];
                            #pragma unroll
                            for (int j = 0; j < 4; j++)
                                acc2[ph][j] = ff2(wv2, P[kw1 + 2 * j], acc2[ph][j]);
                        }
                    }
                }
            }
        }
    }

    if (tid < GROUPS * COUT) {
        float bs = bias[o];
        #pragma unroll
        for (int ph = 0; ph < PH; ph++) {
            int h = h0 + grp * PH + ph;
            #pragma unroll
            for (int j = 0; j < 4; j++) {
                float v0, v1; upk(acc2[ph][j], v0, v1);
                v0 += bs; v1 += bs;
                if (RELU) { v0 = fmaxf(v0, 0.f); v1 = fmaxf(v1, 0.f); }
                int pw = 2 * j;
                if (NCDHW_OUT) {
                    size_t base = (size_t)(b * COUT + o) * SP + (size_t)(d * HH + h) * WW;
                    y[base + pw] = v0; y[base + pw + 1] = v1;
                } else {
                    size_t base = ((size_t)((b * DD + d) * HH + h) * WW + pw) * COUT + o;
                    y[base] = v0; y[base + COUT] = v1;
                }
            }
        }
    }
}

// ---------------- BN: deterministic two-stage stats (channel-last) ----------------
__global__ void bn_part_kernel(const float* __restrict__ y, int C) {
    int blk = blockIdx.x;       // 196 position chunks of 128
    int c = threadIdx.x;
    if (c >= C) return;
    float s = 0.f, q = 0.f;
    int base = blk * 128;
    for (int i = 0; i < 128; i++) {
        float v = y[(size_t)(base + i) * C + c];
        s += v; q += v * v;
    }
    g_ps[blk * CMAX + c] = s;
    g_pq[blk * CMAX + c] = q;
}

// parallel finalize: one block per channel, 256-thread tree reduction over 196 partials
__global__ void bn_fin_kernel(int C) {
    int c = blockIdx.x;
    int t = threadIdx.x;
    __shared__ float sh0[256], sh1[256];
    float s = 0.f, q = 0.f;
    if (t < 196) { s = g_ps[t * CMAX + c]; q = g_pq[t * CMAX + c]; }
    sh0[t] = s; sh1[t] = q;
    __syncthreads();
    for (int st = 128; st > 0; st >>= 1) {
        if (t < st) { sh0[t] += sh0[t + st]; sh1[t] += sh1[t + st]; }
        __syncthreads();
    }
    if (t == 0) {
        float m = sh0[0] / (float)NSP;
        float var = sh1[0] / (float)NSP - m * m;
        g_mean[c] = m;
        g_rstd[c] = rsqrtf(var + 1e-5f);
    }
}

__global__ void bn_apply_kernel(float* __restrict__ y, const float* __restrict__ gma,
                                const float* __restrict__ bta, int C) {
    int idx = blockIdx.x * blockDim.x + threadIdx.x;
    if (idx >= NSP * C) return;
    int c = idx % C;
    y[idx] = (y[idx] - g_mean[c]) * g_rstd[c] * gma[c] + bta[c];
}

// ---------------- deformable conv (channel-last in/out), f32x2 GEMV ----------------
__global__ void deform_kernel(const float* __restrict__ ht,   // channel-last h3 [pos][128]
                              const float* __restrict__ off,  // (B,81,D,H,W) NCDHW
                              const float2* __restrict__ wp,  // [n][c][o] duplicated pairs
                              const float* __restrict__ db,
                              float* __restrict__ y) {        // channel-last out
    __shared__ float s_tile[128 * 36];     // [c][p], row stride 36 floats (144B, 16B-aligned)
    __shared__ int   s_qd[32], s_qh[32], s_qw[32];
    __shared__ float s_td[32], s_th[32], s_tw[32];

    int tid = threadIdx.x;
    int posBase = blockIdx.x * 32;

    ull acc2[16];
    #pragma unroll
    for (int j = 0; j < 16; j++) acc2[j] = 0ull;

    for (int n = 0; n < 27; n++) {
        int kd = n / 9 - 1, kh = (n / 3) % 3 - 1, kw = n % 3 - 1;
        __syncthreads();
        if (tid < 32) {
            int s = posBase + tid;
            int w = s & 7;
            int t = s >> 3;
            int h = t % HH; t /= HH;
            int d = t % DD;
            int b = t / DD;
            size_t obase = (size_t)b * 81 * SP + (size_t)((d * HH + h) * WW + w);
            float od  = off[obase + (size_t)n * SP];
            float oh  = off[obase + (size_t)(27 + n) * SP];
            float ow_ = off[obase + (size_t)(54 + n) * SP];
            float pd = fminf(fmaxf((float)(d + 1 + kd) + od, 0.f), 29.f);
            float ph = fminf(fmaxf((float)(h + 1 + kh) + oh, 0.f), 29.f);
            float pw = fminf(fmaxf((float)(w + 1 + kw) + ow_, 0.f), 9.f);
            float fd = fminf(fmaxf(floorf(pd), 0.f), 28.f);
            float fh = fminf(fmaxf(floorf(ph), 0.f), 28.f);
            float fw = fminf(fmaxf(floorf(pw), 0.f), 8.f);
            s_qd[tid] = (int)fd; s_td[tid] = fminf(fmaxf(pd - fd, 0.f), 1.f);
            s_qh[tid] = (int)fh; s_th[tid] = fminf(fmaxf(ph - fh, 0.f), 1.f);
            s_qw[tid] = (int)fw; s_tw[tid] = fminf(fmaxf(pw - fw, 0.f), 1.f);
        }
        __syncthreads();

        // sampling: thread = channel, loop positions
        for (int p = 0; p < 32; p++) {
            int s = posBase + p;
            int b = s / SP;
            int qd = s_qd[p], qh = s_qh[p], qw = s_qw[p];
            float td = s_td[p], th = s_th[p], tw = s_tw[p];
            float v = 0.f;
            #pragma unroll
            for (int i = 0; i < 2; i++) {
                int zd = qd + i - 1;
                if ((unsigned)zd >= DD) continue;
                float gd = i ? td : (1.f - td);
                #pragma unroll
                for (int j = 0; j < 2; j++) {
                    int zh = qh + j - 1;
                    if ((unsigned)zh >= HH) continue;
                    float gdh = gd * (j ? th : (1.f - th));
                    #pragma unroll
                    for (int k = 0; k < 2; k++) {
                        int zw = qw + k - 1;
                        if ((unsigned)zw >= WW) continue;
                        float g = gdh * (k ? tw : (1.f - tw));
                        size_t base = (size_t)((b * DD + zd) * HH + zh) * WW + zw;
                        v += g * ht[base * CMAX + tid];
                    }
                }
            }
            s_tile[tid * 36 + p] = v;
        }
        __syncthreads();

        // GEMV: thread = output channel; 128-bit broadcast smem reads
        const float2* wrow = wp + (size_t)n * 128 * 128;
        for (int c = 0; c < 128; c++) {
            ull wv2 = *(const ull*)&wrow[c * 128 + tid];
            const ulonglong2* st2 = (const ulonglong2*)(s_tile + c * 36);
            #pragma unroll
            for (int k = 0; k < 8; k++) {
                ulonglong2 q = st2[k];
                acc2[2 * k]     = ff2(wv2, q.x, acc2[2 * k]);
                acc2[2 * k + 1] = ff2(wv2, q.y, acc2[2 * k + 1]);
            }
        }
    }

    float bs = db[tid];
    #pragma unroll
    for (int j = 0; j < 16; j++) {
        float v0, v1; upk(acc2[j], v0, v1);
        int s0 = posBase + 2 * j;
        y[(size_t)s0 * CMAX + tid]       = fmaxf(v0 + bs, 0.f);
        y[(size_t)(s0 + 1) * CMAX + tid] = fmaxf(v1 + bs, 0.f);
    }
}

// ---------------- global avg pool + FC + log_softmax (channel-last) ----------------
__global__ void head_kernel(const float* __restrict__ y, const float* __restrict__ fcw,
                            const float* __restrict__ fcb, float* __restrict__ out) {
    int b = blockIdx.x;
    int c = threadIdx.x;   // 128
    const float* p = y + (size_t)b * SP * CMAX + c;
    float s = 0.f;
    for (int i = 0; i < SP; i++) s += p[(size_t)i * CMAX];
    __shared__ float pooled[128];
    __shared__ float logits[10];
    pooled[c] = s / (float)SP;
    __syncthreads();
    if (c < 10) {
        float l = fcb[c];
        for (int k = 0; k < 128; k++) l += pooled[k] * fcw[c * 128 + k];
        logits[c] = l;
    }
    __syncthreads();
    if (c == 0) {
        float mx = logits[0];
        for (int j = 1; j < 10; j++) mx = fmaxf(mx, logits[j]);
        float se = 0.f;
        for (int j = 0; j < 10; j++) se += expf(logits[j] - mx);
        float lse = mx + logf(se);
        for (int j = 0; j < 10; j++) out[b * 10 + j] = logits[j] - lse;
    }
}

// ---------------- launcher ----------------
extern "C" void kernel_launch(void* const* d_in, const int* in_sizes, int n_in,
                              void* d_out, int out_size) {
    const float* x   = (const float*)d_in[0];
    const float* c1w = (const float*)d_in[1];  const float* c1b = (const float*)d_in[2];
    const float* g1  = (const float*)d_in[3];  const float* b1  = (const float*)d_in[4];
    const float* c2w = (const float*)d_in[5];  const float* c2b = (const float*)d_in[6];
    const float* g2  = (const float*)d_in[7];  const float* b2  = (const float*)d_in[8];
    const float* c3w = (const float*)d_in[9];  const float* c3b = (const float*)d_in[10];
    const float* g3  = (const float*)d_in[11]; const float* b3  = (const float*)d_in[12];
    const float* ow  = (const float*)d_in[13]; const float* ob  = (const float*)d_in[14];
    const float* dw  = (const float*)d_in[15]; const float* db  = (const float*)d_in[16];
    const float* g4  = (const float*)d_in[17]; const float* b4  = (const float*)d_in[18];
    const float* fcw = (const float*)d_in[19]; const float* fcb = (const float*)d_in[20];

    float* out = (float*)d_out;
    float* offsets = out + BATCH * 10;   // logits first, then offsets (NCDHW)

    float *bufA, *bufB; float2* wpair;
    cudaGetSymbolAddress((void**)&bufA, g_bufA);
    cudaGetSymbolAddress((void**)&bufB, g_bufB);
    cudaGetSymbolAddress((void**)&wpair, g_wpair);

    auto grid = [](int total) { return (total + 255) / 256; };

    wtrans_all_kernel<<<(WT_TOTAL + 255) / 256, 256>>>(c1w, c2w, c3w, ow, dw);

    const int CBLK = BATCH * DD * (HH / 4);   // 784

    // layer 1: conv(1->32)+relu, BN   (GROUPS=4, all 128 threads useful)
    conv_cl_kernel<1, 32, 4, 128, true, false><<<CBLK, 128>>>(x, wpair + W1_OFF, c1b, bufA);
    bn_part_kernel<<<196, 128>>>(bufA, 32);
    bn_fin_kernel<<<32, 256>>>(32);
    bn_apply_kernel<<<grid(NSP*32), 256>>>(bufA, g1, b1, 32);

    // layer 2: conv(32->64)+relu, BN   (GROUPS=2 @128thr — measured-best config)
    conv_cl_kernel<32, 64, 2, 128, true, false><<<CBLK, 128>>>(bufA, wpair + W2_OFF, c2b, bufB);
    bn_part_kernel<<<196, 128>>>(bufB, 64);
    bn_fin_kernel<<<64, 256>>>(64);
    bn_apply_kernel<<<grid(NSP*64), 256>>>(bufB, g2, b2, 64);

    // layer 3: conv(64->128)+relu, BN
    conv_cl_kernel<64, 128, 1, 128, true, false><<<CBLK, 128>>>(bufB, wpair + W3_OFF, c3b, bufA);
    bn_part_kernel<<<196, 128>>>(bufA, 128);
    bn_fin_kernel<<<128, 256>>>(128);
    bn_apply_kernel<<<grid(NSP*128), 256>>>(bufA, g3, b3, 128);

    // offsets conv (128->81), no relu, NCDHW straight into output buffer (96 threads)
    conv_cl_kernel<128, 81, 1, 96, false, true><<<CBLK, 96>>>(bufA, wpair + W4_OFF, ob, offsets);

    // deformable conv (128->128) + relu, then BN
    deform_kernel<<<NSP / 32, 128>>>(bufA, offsets, wpair + W5_OFF, db, bufB);
    bn_part_kernel<<<196, 128>>>(bufB, 128);
    bn_fin_kernel<<<128, 256>>>(128);
    bn_apply_kernel<<<grid(NSP*128), 256>>>(bufB, g4, b4, 128);

    // pool + fc + log_softmax
    head_kernel<<<BATCH, 128>>>(bufB, fcw, fcb, out);
}

// round 8
// speedup vs baseline: 1.5667x; 1.0105x over previous
#include <cuda_runtime.h>
#include <math.h>

// ---------------- problem constants ----------------
#define BATCH 4
#define DD 28
#define HH 28
#define WW 8
#define SP (DD*HH*WW)        // 6272
#define NSP (BATCH*SP)       // 25088 = 196*128
#define CMAX 128

typedef unsigned long long ull;

// ---------------- packed f32x2 helpers ----------------
__device__ __forceinline__ ull pk(float a, float b) {
    ull r; asm("mov.b64 %0,{%1,%2};" : "=l"(r) : "f"(a), "f"(b)); return r;
}
__device__ __forceinline__ void upk(ull v, float& a, float& b) {
    asm("mov.b64 {%0,%1},%2;" : "=f"(a), "=f"(b) : "l"(v));
}
__device__ __forceinline__ ull ff2(ull a, ull b, ull c) {
    ull d; asm("fma.rn.f32x2 %0,%1,%2,%3;" : "=l"(d) : "l"(a), "l"(b), "l"(c)); return d;
}

// ---------------- scratch (static device, no allocs) ----------------
__device__ float g_bufA[BATCH*SP*CMAX];   // activations channel-last [b][sp][c]
__device__ float g_bufB[BATCH*SP*CMAX];
__device__ float2 g_wpair[1000000];       // all transposed weights, duplicated pairs
__device__ float g_ps[784*CMAX];          // BN partial sums (deterministic)
__device__ float g_pq[784*CMAX];
__device__ float2 g_bn[4][CMAX];          // per-layer (scale, shift)

// weight region offsets (in float2 elements)
#define W1_OFF 0                         // 27*1*32   = 864
#define W2_OFF 864                       // 27*32*64  = 55296
#define W3_OFF 56160                     // 27*64*128 = 221184
#define W4_OFF 277344                    // 27*128*81 = 279936
#define W5_OFF 557280                    // 27*128*128= 442368  (end 999648)

#define S1 864
#define S2 55296
#define S3 221184
#define S4 279936
#define S5 442368
#define WT_TOTAL (S1+S2+S3+S4+S5)

// ---------------- merged weight transpose: (O,CIN,27) -> pairs [n][ci][o] ----------------
__global__ void wtrans_all_kernel(const float* __restrict__ w1, const float* __restrict__ w2,
                                  const float* __restrict__ w3, const float* __restrict__ w4,
                                  const float* __restrict__ w5) {
    int idx = blockIdx.x * blockDim.x + threadIdx.x;
    if (idx >= WT_TOTAL) return;
    const float* src; float2* dst; int CIN, COUT; int l = idx;
    if (l < S1)              { src = w1; dst = g_wpair + W1_OFF; CIN = 1;   COUT = 32; }
    else if ((l -= S1) < S2) { src = w2; dst = g_wpair + W2_OFF; CIN = 32;  COUT = 64; }
    else if ((l -= S2) < S3) { src = w3; dst = g_wpair + W3_OFF; CIN = 64;  COUT = 128; }
    else if ((l -= S3) < S4) { src = w4; dst = g_wpair + W4_OFF; CIN = 128; COUT = 81; }
    else { l -= S4; src = w5; dst = g_wpair + W5_OFF; CIN = 128; COUT = 128; }
    int n = l % 27;
    int c = (l / 27) % CIN;
    int o = l / (27 * CIN);
    float v = src[l];
    dst[((size_t)n * CIN + c) * COUT + o] = make_float2(v, v);
}

// ---------------- tiled conv3d, channel-last, f32x2 inner, hoisted weights ----------------
// BLOCKT threads, tile: 4h x 8w at fixed d. grid = B*D*(H/4) = 784
// BN_LAYER >= 0: apply g_bn[BN_LAYER] affine to input during staging.
template<int CIN, int COUT, int GROUPS, int BLOCKT, bool RELU, bool NCDHW_OUT, int BN_LAYER>
__global__ void conv_cl_kernel(const float* __restrict__ x, const float2* __restrict__ wp,
                               const float* __restrict__ bias, float* __restrict__ y) {
    constexpr int CH = (CIN < 16) ? CIN : 16;
    constexpr int NCH = CIN / CH;
    constexpr int PH = 4 / GROUPS;           // h-rows per thread
    __shared__ float xs[CH][18][12];   // [ci][zd*6+zh][zw padded 10->12]

    int tid = threadIdx.x;
    int blk = blockIdx.x;
    int hb = blk % 7;
    int d  = (blk / 7) % DD;
    int b  = blk / (7 * DD);
    int h0 = hb * 4;
    int grp = tid / COUT;
    if (grp > GROUPS - 1) grp = GROUPS - 1;
    int o = tid - grp * COUT;
    if (o >= COUT) o = 0;

    ull acc2[PH][4];
    #pragma unroll
    for (int ph = 0; ph < PH; ph++)
        #pragma unroll
        for (int j = 0; j < 4; j++) acc2[ph][j] = 0ull;

    for (int cc = 0; cc < NCH; cc++) {
        __syncthreads();
        // stage input tile (zero-padded halo), coalesced over ci
        for (int i = tid; i < 180 * CH; i += BLOCKT) {
            int ci, pos;
            if (CH == 16) { ci = i & 15; pos = i >> 4; }
            else          { ci = i % CH; pos = i / CH; }
            int zw = pos % 10;
            int zh = (pos / 10) % 6;
            int zd = pos / 60;
            int gd = d + zd - 1, gh = h0 + zh - 1, gw = zw - 1;
            float v = 0.0f;
            int cg = cc * CH + ci;
            if ((unsigned)gd < DD && (unsigned)gh < HH && (unsigned)gw < WW) {
                v = x[((size_t)((b * DD + gd) * HH + gh) * WW + gw) * CIN + cg];
                if (BN_LAYER >= 0) { float2 t = g_bn[BN_LAYER][cg]; v = fmaf(v, t.x, t.y); }
            }
            xs[ci][zd * 6 + zh][zw] = v;
        }
        __syncthreads();

        for (int ci = 0; ci < CH; ci++) {
            int cglob = cc * CH + ci;
            #pragma unroll
            for (int zd = 0; zd < 3; zd++) {
                // hoist the 9 taps of this zd-plane into registers (one LDG each)
                ull wreg[9];
                #pragma unroll
                for (int t = 0; t < 9; t++)
                    wreg[t] = *(const ull*)&wp[((size_t)(zd * 9 + t) * CIN + cglob) * COUT + o];
                #pragma unroll
                for (int zl = 0; zl < PH + 2; zl++) {
                    const float2* row = (const float2*)&xs[ci][zd * 6 + grp * PH + zl][0];
                    float2 e0 = row[0], e1 = row[1], e2 = row[2], e3 = row[3], e4 = row[4];
                    ull P[9];
                    P[0] = pk(e0.x, e0.y); P[2] = pk(e1.x, e1.y); P[4] = pk(e2.x, e2.y);
                    P[6] = pk(e3.x, e3.y); P[8] = pk(e4.x, e4.y);
                    P[1] = pk(e0.y, e1.x); P[3] = pk(e1.y, e2.x);
                    P[5] = pk(e2.y, e3.x); P[7] = pk(e3.y, e4.x);
                    #pragma unroll
                    for (int ph = 0; ph < PH; ph++) {
                        int kh1 = zl - ph;               // kh+1
                        if (kh1 < 0 || kh1 > 2) continue; // constant-folds
                        #pragma unroll
                        for (int kw1 = 0; kw1 < 3; kw1++) {
                            ull wv2 = wreg[kh1 * 3 + kw1];
                            #pragma unroll
                            for (int j = 0; j < 4; j++)
                                acc2[ph][j] = ff2(wv2, P[kw1 + 2 * j], acc2[ph][j]);
                        }
                    }
                }
            }
        }
    }

    if (tid < GROUPS * COUT) {
        float bs = bias[o];
        #pragma unroll
        for (int ph = 0; ph < PH; ph++) {
            int h = h0 + grp * PH + ph;
            #pragma unroll
            for (int j = 0; j < 4; j++) {
                float v0, v1; upk(acc2[ph][j], v0, v1);
                v0 += bs; v1 += bs;
                if (RELU) { v0 = fmaxf(v0, 0.f); v1 = fmaxf(v1, 0.f); }
                int pw = 2 * j;
                if (NCDHW_OUT) {
                    size_t base = (size_t)(b * COUT + o) * SP + (size_t)(d * HH + h) * WW;
                    y[base + pw] = v0; y[base + pw + 1] = v1;
                } else {
                    size_t base = ((size_t)((b * DD + d) * HH + h) * WW + pw) * COUT + o;
                    y[base] = v0; y[base + COUT] = v1;
                }
            }
        }
    }
}

// ---------------- BN: deterministic two-stage stats (channel-last) ----------------
__global__ void bn_part_kernel(const float* __restrict__ y, int C) {
    int blk = blockIdx.x;       // 196 position chunks of 128
    int c = threadIdx.x;
    if (c >= C) return;
    float s = 0.f, q = 0.f;
    int base = blk * 128;
    for (int i = 0; i < 128; i++) {
        float v = y[(size_t)(base + i) * C + c];
        s += v; q += v * v;
    }
    g_ps[blk * CMAX + c] = s;
    g_pq[blk * CMAX + c] = q;
}

// parallel finalize: one block per channel -> (scale, shift)
__global__ void bn_fin_kernel(const float* __restrict__ gma, const float* __restrict__ bta,
                              int layer) {
    int c = blockIdx.x;
    int t = threadIdx.x;
    __shared__ float sh0[256], sh1[256];
    float s = 0.f, q = 0.f;
    if (t < 196) { s = g_ps[t * CMAX + c]; q = g_pq[t * CMAX + c]; }
    sh0[t] = s; sh1[t] = q;
    __syncthreads();
    for (int st = 128; st > 0; st >>= 1) {
        if (t < st) { sh0[t] += sh0[t + st]; sh1[t] += sh1[t + st]; }
        __syncthreads();
    }
    if (t == 0) {
        float m = sh0[0] / (float)NSP;
        float var = sh1[0] / (float)NSP - m * m;
        float r = rsqrtf(var + 1e-5f);
        float sc = r * gma[c];
        g_bn[layer][c] = make_float2(sc, bta[c] - m * sc);
    }
}

// in-place BN apply (only needed for layer 3, consumed by offset conv + deform)
__global__ void bn_apply_kernel(float* __restrict__ y, int layer, int C) {
    int idx = blockIdx.x * blockDim.x + threadIdx.x;
    if (idx >= NSP * C) return;
    int c = idx % C;
    float2 t = g_bn[layer][c];
    y[idx] = fmaf(y[idx], t.x, t.y);
}

// ---------------- deformable conv (channel-last in/out), f32x2 GEMV ----------------
__global__ void deform_kernel(const float* __restrict__ ht,   // channel-last h3 [pos][128]
                              const float* __restrict__ off,  // (B,81,D,H,W) NCDHW
                              const float2* __restrict__ wp,  // [n][c][o] duplicated pairs
                              const float* __restrict__ db,
                              float* __restrict__ y) {        // channel-last out
    __shared__ float s_tile[128 * 36];     // [c][p], row stride 36 floats (144B, 16B-aligned)
    __shared__ int   s_qd[32], s_qh[32], s_qw[32];
    __shared__ float s_td[32], s_th[32], s_tw[32];

    int tid = threadIdx.x;
    int posBase = blockIdx.x * 32;

    ull acc2[16];
    #pragma unroll
    for (int j = 0; j < 16; j++) acc2[j] = 0ull;

    for (int n = 0; n < 27; n++) {
        int kd = n / 9 - 1, kh = (n / 3) % 3 - 1, kw = n % 3 - 1;
        __syncthreads();
        if (tid < 32) {
            int s = posBase + tid;
            int w = s & 7;
            int t = s >> 3;
            int h = t % HH; t /= HH;
            int d = t % DD;
            int b = t / DD;
            size_t obase = (size_t)b * 81 * SP + (size_t)((d * HH + h) * WW + w);
            float od  = off[obase + (size_t)n * SP];
            float oh  = off[obase + (size_t)(27 + n) * SP];
            float ow_ = off[obase + (size_t)(54 + n) * SP];
            float pd = fminf(fmaxf((float)(d + 1 + kd) + od, 0.f), 29.f);
            float ph = fminf(fmaxf((float)(h + 1 + kh) + oh, 0.f), 29.f);
            float pw = fminf(fmaxf((float)(w + 1 + kw) + ow_, 0.f), 9.f);
            float fd = fminf(fmaxf(floorf(pd), 0.f), 28.f);
            float fh = fminf(fmaxf(floorf(ph), 0.f), 28.f);
            float fw = fminf(fmaxf(floorf(pw), 0.f), 8.f);
            s_qd[tid] = (int)fd; s_td[tid] = fminf(fmaxf(pd - fd, 0.f), 1.f);
            s_qh[tid] = (int)fh; s_th[tid] = fminf(fmaxf(ph - fh, 0.f), 1.f);
            s_qw[tid] = (int)fw; s_tw[tid] = fminf(fmaxf(pw - fw, 0.f), 1.f);
        }
        __syncthreads();

        // sampling: thread = channel, loop positions
        for (int p = 0; p < 32; p++) {
            int s = posBase + p;
            int b = s / SP;
            int qd = s_qd[p], qh = s_qh[p], qw = s_qw[p];
            float td = s_td[p], th = s_th[p], tw = s_tw[p];
            float v = 0.f;
            #pragma unroll
            for (int i = 0; i < 2; i++) {
                int zd = qd + i - 1;
                if ((unsigned)zd >= DD) continue;
                float gd = i ? td : (1.f - td);
                #pragma unroll
                for (int j = 0; j < 2; j++) {
                    int zh = qh + j - 1;
                    if ((unsigned)zh >= HH) continue;
                    float gdh = gd * (j ? th : (1.f - th));
                    #pragma unroll
                    for (int k = 0; k < 2; k++) {
                        int zw = qw + k - 1;
                        if ((unsigned)zw >= WW) continue;
                        float g = gdh * (k ? tw : (1.f - tw));
                        size_t base = (size_t)((b * DD + zd) * HH + zh) * WW + zw;
                        v += g * ht[base * CMAX + tid];
                    }
                }
            }
            s_tile[tid * 36 + p] = v;
        }
        __syncthreads();

        // GEMV: thread = output channel; 128-bit broadcast smem reads
        const float2* wrow = wp + (size_t)n * 128 * 128;
        for (int c = 0; c < 128; c++) {
            ull wv2 = *(const ull*)&wrow[c * 128 + tid];
            const ulonglong2* st2 = (const ulonglong2*)(s_tile + c * 36);
            #pragma unroll
            for (int k = 0; k < 8; k++) {
                ulonglong2 q = st2[k];
                acc2[2 * k]     = ff2(wv2, q.x, acc2[2 * k]);
                acc2[2 * k + 1] = ff2(wv2, q.y, acc2[2 * k + 1]);
            }
        }
    }

    float bs = db[tid];
    #pragma unroll
    for (int j = 0; j < 16; j++) {
        float v0, v1; upk(acc2[j], v0, v1);
        int s0 = posBase + 2 * j;
        y[(size_t)s0 * CMAX + tid]       = fmaxf(v0 + bs, 0.f);
        y[(size_t)(s0 + 1) * CMAX + tid] = fmaxf(v1 + bs, 0.f);
    }
}

// ---------------- global avg pool (+BN4) + FC + log_softmax ----------------
__global__ void head_kernel(const float* __restrict__ y, const float* __restrict__ fcw,
                            const float* __restrict__ fcb, float* __restrict__ out) {
    int b = blockIdx.x;
    int c = threadIdx.x;   // 128
    const float* p = y + (size_t)b * SP * CMAX + c;
    float s = 0.f;
    for (int i = 0; i < SP; i++) s += p[(size_t)i * CMAX];
    __shared__ float pooled[128];
    __shared__ float logits[10];
    float2 bn = g_bn[3][c];
    pooled[c] = fmaf(s / (float)SP, bn.x, bn.y);
    __syncthreads();
    if (c < 10) {
        float l = fcb[c];
        for (int k = 0; k < 128; k++) l += pooled[k] * fcw[c * 128 + k];
        logits[c] = l;
    }
    __syncthreads();
    if (c == 0) {
        float mx = logits[0];
        for (int j = 1; j < 10; j++) mx = fmaxf(mx, logits[j]);
        float se = 0.f;
        for (int j = 0; j < 10; j++) se += expf(logits[j] - mx);
        float lse = mx + logf(se);
        for (int j = 0; j < 10; j++) out[b * 10 + j] = logits[j] - lse;
    }
}

// ---------------- launcher ----------------
extern "C" void kernel_launch(void* const* d_in, const int* in_sizes, int n_in,
                              void* d_out, int out_size) {
    const float* x   = (const float*)d_in[0];
    const float* c1w = (const float*)d_in[1];  const float* c1b = (const float*)d_in[2];
    const float* g1  = (const float*)d_in[3];  const float* b1  = (const float*)d_in[4];
    const float* c2w = (const float*)d_in[5];  const float* c2b = (const float*)d_in[6];
    const float* g2  = (const float*)d_in[7];  const float* b2  = (const float*)d_in[8];
    const float* c3w = (const float*)d_in[9];  const float* c3b = (const float*)d_in[10];
    const float* g3  = (const float*)d_in[11]; const float* b3  = (const float*)d_in[12];
    const float* ow  = (const float*)d_in[13]; const float* ob  = (const float*)d_in[14];
    const float* dw  = (const float*)d_in[15]; const float* db  = (const float*)d_in[16];
    const float* g4  = (const float*)d_in[17]; const float* b4  = (const float*)d_in[18];
    const float* fcw = (const float*)d_in[19]; const float* fcb = (const float*)d_in[20];

    float* out = (float*)d_out;
    float* offsets = out + BATCH * 10;   // logits first, then offsets (NCDHW)

    float *bufA, *bufB; float2* wpair;
    cudaGetSymbolAddress((void**)&bufA, g_bufA);
    cudaGetSymbolAddress((void**)&bufB, g_bufB);
    cudaGetSymbolAddress((void**)&wpair, g_wpair);

    auto grid = [](int total) { return (total + 255) / 256; };

    wtrans_all_kernel<<<(WT_TOTAL + 255) / 256, 256>>>(c1w, c2w, c3w, ow, dw);

    const int CBLK = BATCH * DD * (HH / 4);   // 784

    // layer 1: conv(1->32)+relu -> stats (BN0 fused into conv2 staging)
    conv_cl_kernel<1, 32, 4, 128, true, false, -1><<<CBLK, 128>>>(x, wpair + W1_OFF, c1b, bufA);
    bn_part_kernel<<<196, 128>>>(bufA, 32);
    bn_fin_kernel<<<32, 256>>>(g1, b1, 0);

    // layer 2: conv(32->64)+relu (applies BN0 at staging) -> stats (BN1 fused into conv3)
    conv_cl_kernel<32, 64, 2, 128, true, false, 0><<<CBLK, 128>>>(bufA, wpair + W2_OFF, c2b, bufB);
    bn_part_kernel<<<196, 128>>>(bufB, 64);
    bn_fin_kernel<<<64, 256>>>(g2, b2, 1);

    // layer 3: conv(64->128)+relu (applies BN1 at staging) -> stats, explicit BN2 apply
    conv_cl_kernel<64, 128, 1, 128, true, false, 1><<<CBLK, 128>>>(bufB, wpair + W3_OFF, c3b, bufA);
    bn_part_kernel<<<196, 128>>>(bufA, 128);
    bn_fin_kernel<<<128, 256>>>(g3, b3, 2);
    bn_apply_kernel<<<grid(NSP*128), 256>>>(bufA, 2, 128);

    // offsets conv (128->81), input already BN'd, NCDHW into output buffer (96 threads)
    conv_cl_kernel<128, 81, 1, 96, false, true, -1><<<CBLK, 96>>>(bufA, wpair + W4_OFF, ob, offsets);

    // deformable conv (128->128) + relu -> stats (BN3 folded into head)
    deform_kernel<<<NSP / 32, 128>>>(bufA, offsets, wpair + W5_OFF, db, bufB);
    bn_part_kernel<<<196, 128>>>(bufB, 128);
    bn_fin_kernel<<<128, 256>>>(g4, b4, 3);

    // pool (+BN3 affine) + fc + log_softmax
    head_kernel<<<BATCH, 128>>>(bufB, fcw, fcb, out);
}